// round 14
// baseline (speedup 1.0000x reference)
#include <cuda_runtime.h>
#include <cuda_bf16.h>
#include <cstdint>

#define NB_B 4096
#define ND 16
#define NM 4
#define NR 2048
#define NC 10
#define NDP1 17
#define MU 8.5f

// cons planes, mean-centered bf16x2, pair-interleaved for LDG.128:
//   g_consA[q] = {p0/even, p0/odd, p1/even, p1/odd}
//   g_consB[q] = {p2/even, p2/odd, p3/even, p3/odd}
//   g_consC[q] = {p4/even, p4/odd}
__device__ uint4    g_consA[NR / 2];
__device__ uint4    g_consB[NR / 2];
__device__ uint2    g_consC[NR / 2];
__device__ unsigned g_rpack[NR];                        // 16 dims x 2 bits
__device__ float    g_inv[NB_B];
__device__ float    g_norm_scratch[(size_t)NB_B * NR];  // fallback only

__device__ __forceinline__ float bf16lo(unsigned w) {
    return __uint_as_float(w << 16);
}
__device__ __forceinline__ float bf16hi(unsigned w) {
    return __uint_as_float(w & 0xffff0000u);
}

// ---------------------------------------------------------------------------
// K0: coalesced prep. 128 blocks x 256 thr; 16 rules/block (R10-proven).
// ---------------------------------------------------------------------------
__global__ __launch_bounds__(256) void prep_kernel(
    const float* __restrict__ cons, const int* __restrict__ rules) {
    __shared__ float sc[16 * NDP1 * NC];   // 10880 B
    __shared__ int   sr[16 * ND];

    const int tid = threadIdx.x;
    const int r0  = blockIdx.x * 16;

    const float* cbase = cons + (size_t)r0 * NDP1 * NC;
#pragma unroll
    for (int i = tid; i < 16 * NDP1 * NC; i += 256) sc[i] = cbase[i];
    sr[tid] = rules[r0 * ND + tid];        // exactly 256 ints
    __syncthreads();

    if (tid < 80) {
        const int rl = tid / 5, p = tid % 5;
        const float* row = sc + rl * NDP1 * NC + 2 * p;
        float s0 = 0.f, s1 = 0.f;
#pragma unroll
        for (int j = 0; j < NDP1; ++j) {
            s0 += row[j * NC];
            s1 += row[j * NC + 1];
        }
        const int gw = r0 + rl, q = gw >> 1, r1 = gw & 1;
        __nv_bfloat162 h = __floats2bfloat162_rn(s0 - MU, s1 - MU);
        unsigned wb = *(unsigned*)&h;
        if (p == 0)      ((unsigned*)g_consA)[q * 4 + 0 + r1] = wb;
        else if (p == 1) ((unsigned*)g_consA)[q * 4 + 2 + r1] = wb;
        else if (p == 2) ((unsigned*)g_consB)[q * 4 + 0 + r1] = wb;
        else if (p == 3) ((unsigned*)g_consB)[q * 4 + 2 + r1] = wb;
        else             ((unsigned*)g_consC)[q * 2 + r1]     = wb;
    } else if (tid < 96) {
        const int rl = tid - 80;
        unsigned pk = 0;
#pragma unroll
        for (int d = 0; d < ND; ++d)
            pk |= ((unsigned)sr[rl * ND + d] & 3u) << (2 * d);
        g_rpack[r0 + rl] = pk;
    }
}

// ---------------------------------------------------------------------------
// K1 (fused, ONE pass, scalar FMA, QUAD tables): 128 thr = 4 warps = one
// batch-pair. Tables: tab4[tt][i8] covers 4 dims (256 entries, float2
// batch-paired) -> only 4 LDS lookups per rule. rpack byte tt IS the index.
// Per k-iter: 2 rules x (4 lookups + 3 float2 adds + 2 exp), STG
// unnormalized f, scalar bf16 cons GEMV into float acc[2][10].
// ---------------------------------------------------------------------------
__global__ __launch_bounds__(128, 8) void fused_kernel(
    const float* __restrict__ x,
    const float* __restrict__ centers,
    const float* __restrict__ widths,
    float* __restrict__ norm_out,
    float* __restrict__ xext_out,
    float* __restrict__ out,
    int write_xext) {
    __shared__ float  s_e[2][64];
    __shared__ float2 s_tab2[8][16];     // pair tables (build scratch)
    __shared__ float2 s_tab4[4][256];    // quad tables: 8 KB
    __shared__ float  s_sum[4][2];
    __shared__ float  s_acc[4][2][NC];
    __shared__ float  s_sx[2];

    const int tid  = threadIdx.x;
    const int w    = tid >> 5;
    const int lane = tid & 31;
    const int bA   = blockIdx.x * 2;
    const int bB   = bA + 1;

    // setup: warps 0,1 build per-batch e and pair tables (warp h -> comp h)
    if (w < 2) {
        const int b = bA + w;
        float xv = (lane < ND) ? x[b * ND + lane] : 0.f;
        float sx = xv;
#pragma unroll
        for (int off = 16; off > 0; off >>= 1)
            sx += __shfl_xor_sync(0xffffffffu, sx, off);
        sx += 1.f;
        if (lane == 0) s_sx[w] = sx;
        if (write_xext) {
            if (lane < ND) xext_out[b * NDP1 + lane] = xv;
            if (lane == ND) xext_out[b * NDP1 + ND] = 1.f;
        }
#pragma unroll
        for (int k = lane; k < 64; k += 32) {
            int d = k >> 2, m = k & 3;
            float c  = centers[d * NM + m];
            float wd = widths[d * NM + m];
            float xd = __shfl_sync(0xffffffffu, xv, d);
            float dx = xd - c;
            s_e[w][k] = -(dx * dx) / (2.f * wd * wd);
        }
        __syncwarp();
#pragma unroll
        for (int k = lane; k < 128; k += 32) {
            int t = k >> 4, i = k & 15;
            float v = s_e[w][(2 * t) * 4 + (i & 3)] +
                      s_e[w][(2 * t + 1) * 4 + (i >> 2)];
            if (w == 0) s_tab2[t][i].x = v;
            else        s_tab2[t][i].y = v;
        }
    }
    __syncthreads();

    // all 128 threads build quad tables: tab4[tt][i] = tab2[2tt][i&15] +
    // tab2[2tt+1][i>>4]  (8 entries per thread)
#pragma unroll
    for (int k = tid; k < 1024; k += 128) {
        const int tt = k >> 8, i = k & 255;
        float2 a = s_tab2[2 * tt][i & 15];
        float2 b2 = s_tab2[2 * tt + 1][i >> 4];
        s_tab4[tt][i] = make_float2(a.x + b2.x, a.y + b2.y);
    }
    __syncthreads();

    const uint2* __restrict__ rp = (const uint2*)g_rpack;
    float2* fpA = (float2*)(norm_out + (size_t)bA * NR);
    float2* fpB = (float2*)(norm_out + (size_t)bB * NR);

    float accA[NC], accB[NC];
#pragma unroll
    for (int c = 0; c < NC; ++c) { accA[c] = 0.f; accB[c] = 0.f; }
    float sumA = 0.f, sumB = 0.f;

#pragma unroll
    for (int k = 0; k < 8; ++k) {
        const int q = (w * 8 + k) * 32 + lane;    // rule-pair index
        uint2 pp = rp[q];
        // rule 0: 4 quad lookups (bytes of pp.x)
        float2 a0 = s_tab4[0][pp.x & 255];
        float2 a1 = s_tab4[1][(pp.x >> 8) & 255];
        float2 a2 = s_tab4[2][(pp.x >> 16) & 255];
        float2 a3 = s_tab4[3][pp.x >> 24];
        float2 b0 = s_tab4[0][pp.y & 255];
        float2 b1 = s_tab4[1][(pp.y >> 8) & 255];
        float2 b2 = s_tab4[2][(pp.y >> 16) & 255];
        float2 b3 = s_tab4[3][pp.y >> 24];
        float s0A = (a0.x + a1.x) + (a2.x + a3.x);
        float s0B = (a0.y + a1.y) + (a2.y + a3.y);
        float s1A = (b0.x + b1.x) + (b2.x + b3.x);
        float s1B = (b0.y + b1.y) + (b2.y + b3.y);

        float f0A = __expf(s0A), f1A = __expf(s1A);
        float f0B = __expf(s0B), f1B = __expf(s1B);
        sumA += f0A + f1A;
        sumB += f0B + f1B;
        fpA[q] = make_float2(f0A, f1A);           // UNNORMALIZED f
        fpB[q] = make_float2(f0B, f1B);

        uint4 cA = g_consA[q];
        uint4 cB = g_consB[q];
        uint2 cC = g_consC[q];
        const unsigned we[5] = {cA.x, cA.z, cB.x, cB.z, cC.x};
        const unsigned wo[5] = {cA.y, cA.w, cB.y, cB.w, cC.y};
#pragma unroll
        for (int p = 0; p < 5; ++p) {
            const float celo = bf16lo(we[p]), cehi = bf16hi(we[p]);
            const float colo = bf16lo(wo[p]), cohi = bf16hi(wo[p]);
            accA[2 * p]     = fmaf(f0A, celo, fmaf(f1A, colo, accA[2 * p]));
            accA[2 * p + 1] = fmaf(f0A, cehi, fmaf(f1A, cohi, accA[2 * p + 1]));
            accB[2 * p]     = fmaf(f0B, celo, fmaf(f1B, colo, accB[2 * p]));
            accB[2 * p + 1] = fmaf(f0B, cehi, fmaf(f1B, cohi, accB[2 * p + 1]));
        }
    }

#pragma unroll
    for (int off = 16; off > 0; off >>= 1) {
        sumA += __shfl_xor_sync(0xffffffffu, sumA, off);
        sumB += __shfl_xor_sync(0xffffffffu, sumB, off);
#pragma unroll
        for (int c = 0; c < NC; ++c) {
            accA[c] += __shfl_xor_sync(0xffffffffu, accA[c], off);
            accB[c] += __shfl_xor_sync(0xffffffffu, accB[c], off);
        }
    }
    if (lane == 0) {
        s_sum[w][0] = sumA;
        s_sum[w][1] = sumB;
#pragma unroll
        for (int c = 0; c < NC; ++c) {
            s_acc[w][0][c] = accA[c];
            s_acc[w][1][c] = accB[c];
        }
    }
    __syncthreads();

    if (tid < 2) {                        // g_inv for the scale kernel
        float tot = s_sum[0][tid] + s_sum[1][tid] +
                    s_sum[2][tid] + s_sum[3][tid];
        g_inv[bA + tid] = 1.f / (tot + 1e-9f);
    }
    if (tid < 20) {
        const int h = tid / 10, c = tid % 10;
        float a = s_acc[0][h][c] + s_acc[1][h][c] +
                  s_acc[2][h][c] + s_acc[3][h][c];
        float tot = s_sum[0][h] + s_sum[1][h] + s_sum[2][h] + s_sum[3][h];
        float inv = 1.f / (tot + 1e-9f);
        // acc is on unnormalized f: out = (acc + MU*tot) * inv * sx
        out[(size_t)(bA + h) * NC + c] = (a + MU * tot) * inv * s_sx[h];
    }
}

// ---------------------------------------------------------------------------
// K2: normalize in place: norm[b][r] *= inv[b]. L2-resident stream.
// ---------------------------------------------------------------------------
__global__ __launch_bounds__(256) void scale_kernel(float* __restrict__ norm) {
    const int b = blockIdx.x;
    const float inv = g_inv[b];
    float4* p = (float4*)(norm + (size_t)b * NR);
#pragma unroll
    for (int i = threadIdx.x; i < NR / 4; i += 256) {
        float4 v = p[i];
        v.x *= inv; v.y *= inv; v.z *= inv; v.w *= inv;
        p[i] = v;
    }
}

// ---------------------------------------------------------------------------
extern "C" void kernel_launch(void* const* d_in, const int* in_sizes, int n_in,
                              void* d_out, int out_size) {
    const float* x       = (const float*)d_in[0];
    const float* centers = (const float*)d_in[1];
    const float* widths  = (const float*)d_in[2];
    const float* cons    = (const float*)d_in[3];
    const int*   rules   = (const int*)d_in[4];
    float* out = (float*)d_out;

    const long long TOTAL = (long long)NB_B * NC + (long long)NB_B * NR +
                            (long long)NB_B * NDP1;

    float* out_p = out;
    float* norm_p;
    float* xext_p = out;
    int write_xext = 0;

    if ((long long)out_size == TOTAL) {
        norm_p = out + (size_t)NB_B * NC;
        xext_p = out + (size_t)NB_B * NC + (size_t)NB_B * NR;
        write_xext = 1;
    } else {
        void* sp = nullptr;
        cudaGetSymbolAddress(&sp, g_norm_scratch);
        norm_p = (float*)sp;
    }

    prep_kernel<<<NR / 16, 256>>>(cons, rules);
    fused_kernel<<<NB_B / 2, 128>>>(x, centers, widths, norm_p,
                                    xext_p, out_p, write_xext);
    scale_kernel<<<NB_B, 256>>>(norm_p);
}

// round 15
// speedup vs baseline: 1.2979x; 1.2979x over previous
#include <cuda_runtime.h>
#include <cuda_bf16.h>
#include <cstdint>

#define NB_B 4096
#define ND 16
#define NM 4
#define NR 2048
#define NC 10
#define NDP1 17
#define MU 8.5f

// cons planes, mean-centered bf16x2, pair-interleaved for LDG.128:
//   g_consA[q] = {p0/even, p0/odd, p1/even, p1/odd}
//   g_consB[q] = {p2/even, p2/odd, p3/even, p3/odd}
//   g_consC[q] = {p4/even, p4/odd}
__device__ uint4    g_consA[NR / 2];
__device__ uint4    g_consB[NR / 2];
__device__ uint2    g_consC[NR / 2];
__device__ unsigned g_rpack[NR];                        // 16 dims x 2 bits
__device__ float    g_norm_scratch[(size_t)NB_B * NR];  // fallback only

__device__ __forceinline__ float bf16lo(unsigned w) {
    return __uint_as_float(w << 16);
}
__device__ __forceinline__ float bf16hi(unsigned w) {
    return __uint_as_float(w & 0xffff0000u);
}

// sum of 8 batch-paired table entries selected by the 16 2-bit fields of u
__device__ __forceinline__ float2 lookup8(const float2 (*tab)[16], unsigned u) {
    float2 r = tab[0][u & 15];
#pragma unroll
    for (int t = 1; t < 8; ++t) {
        float2 a = tab[t][(u >> (4 * t)) & 15];
        r.x += a.x;
        r.y += a.y;
    }
    return r;
}

// ---------------------------------------------------------------------------
// K0: coalesced prep. 128 blocks x 256 thr; 16 rules/block (R10-proven).
// ---------------------------------------------------------------------------
__global__ __launch_bounds__(256) void prep_kernel(
    const float* __restrict__ cons, const int* __restrict__ rules) {
    __shared__ float sc[16 * NDP1 * NC];   // 10880 B
    __shared__ int   sr[16 * ND];

    const int tid = threadIdx.x;
    const int r0  = blockIdx.x * 16;

    const float* cbase = cons + (size_t)r0 * NDP1 * NC;
#pragma unroll
    for (int i = tid; i < 16 * NDP1 * NC; i += 256) sc[i] = cbase[i];
    sr[tid] = rules[r0 * ND + tid];        // exactly 256 ints
    __syncthreads();

    if (tid < 80) {
        const int rl = tid / 5, p = tid % 5;
        const float* row = sc + rl * NDP1 * NC + 2 * p;
        float s0 = 0.f, s1 = 0.f;
#pragma unroll
        for (int j = 0; j < NDP1; ++j) {
            s0 += row[j * NC];
            s1 += row[j * NC + 1];
        }
        const int gw = r0 + rl, q = gw >> 1, r1 = gw & 1;
        __nv_bfloat162 h = __floats2bfloat162_rn(s0 - MU, s1 - MU);
        unsigned wb = *(unsigned*)&h;
        if (p == 0)      ((unsigned*)g_consA)[q * 4 + 0 + r1] = wb;
        else if (p == 1) ((unsigned*)g_consA)[q * 4 + 2 + r1] = wb;
        else if (p == 2) ((unsigned*)g_consB)[q * 4 + 0 + r1] = wb;
        else if (p == 3) ((unsigned*)g_consB)[q * 4 + 2 + r1] = wb;
        else             ((unsigned*)g_consC)[q * 2 + r1]     = wb;
    } else if (tid < 96) {
        const int rl = tid - 80;
        unsigned pk = 0;
#pragma unroll
        for (int d = 0; d < ND; ++d)
            pk |= ((unsigned)sr[rl * ND + d] & 3u) << (2 * d);
        g_rpack[r0 + rl] = pk;
    }
}

// ---------------------------------------------------------------------------
// K1 (fused, scalar FMA + smem f-park): 128 thr = 4 warps = one batch-pair.
// PASS 1 (R13 engine): pair-table float2 lookups, exp, park UNNORMALIZED f
// in smem (STS.64), scalar bf16 cons GEMV into float acc[2][10] on
// unnormalized f. Reduce -> tot/inv.
// PASS 2: lane owns 2 adjacent pairs -> LDS.128 parked f, scalar mul by inv,
// STG.128 normalized norm_fs. No scale kernel.
// ---------------------------------------------------------------------------
__global__ __launch_bounds__(128, 9) void fused_kernel(
    const float* __restrict__ x,
    const float* __restrict__ centers,
    const float* __restrict__ widths,
    float* __restrict__ norm_out,
    float* __restrict__ xext_out,
    float* __restrict__ out,
    int write_xext) {
    __shared__ __align__(16) float2 s_f[2][NR / 2];  // parked f: 16 KB
    __shared__ float  s_e[2][64];
    __shared__ float2 s_tab[8][16];      // [table][idx] = (eA, eB)
    __shared__ float  s_sum[4][2];
    __shared__ float  s_acc[4][2][NC];
    __shared__ float  s_sx[2];

    const int tid  = threadIdx.x;
    const int w    = tid >> 5;
    const int lane = tid & 31;
    const int bA   = blockIdx.x * 2;
    const int bB   = bA + 1;

    // setup: warps 0,1 build per-batch tables (warp h -> component h)
    if (w < 2) {
        const int b = bA + w;
        float xv = (lane < ND) ? x[b * ND + lane] : 0.f;
        float sx = xv;
#pragma unroll
        for (int off = 16; off > 0; off >>= 1)
            sx += __shfl_xor_sync(0xffffffffu, sx, off);
        sx += 1.f;
        if (lane == 0) s_sx[w] = sx;
        if (write_xext) {
            if (lane < ND) xext_out[b * NDP1 + lane] = xv;
            if (lane == ND) xext_out[b * NDP1 + ND] = 1.f;
        }
#pragma unroll
        for (int k = lane; k < 64; k += 32) {
            int d = k >> 2, m = k & 3;
            float c  = centers[d * NM + m];
            float wd = widths[d * NM + m];
            float xd = __shfl_sync(0xffffffffu, xv, d);
            float dx = xd - c;
            s_e[w][k] = -(dx * dx) / (2.f * wd * wd);
        }
        __syncwarp();
#pragma unroll
        for (int k = lane; k < 128; k += 32) {
            int t = k >> 4, i = k & 15;
            float v = s_e[w][(2 * t) * 4 + (i & 3)] +
                      s_e[w][(2 * t + 1) * 4 + (i >> 2)];
            if (w == 0) s_tab[t][i].x = v;
            else        s_tab[t][i].y = v;
        }
    }
    __syncthreads();

    const uint2* __restrict__ rp = (const uint2*)g_rpack;

    float accA[NC], accB[NC];
#pragma unroll
    for (int c = 0; c < NC; ++c) { accA[c] = 0.f; accB[c] = 0.f; }
    float sumA = 0.f, sumB = 0.f;

    // ---- PASS 1: lookups, exp, park f, scalar GEMV on unnormalized f ----
#pragma unroll
    for (int k = 0; k < 8; ++k) {
        const int q = (w * 8 + k) * 32 + lane;    // rule-pair index
        uint2 pp = rp[q];
        float2 s0 = lookup8(s_tab, pp.x);
        float2 s1 = lookup8(s_tab, pp.y);
        float f0A = __expf(s0.x), f1A = __expf(s1.x);
        float f0B = __expf(s0.y), f1B = __expf(s1.y);
        sumA += f0A + f1A;
        sumB += f0B + f1B;
        s_f[0][q] = make_float2(f0A, f1A);        // park UNNORMALIZED f
        s_f[1][q] = make_float2(f0B, f1B);

        uint4 cA = g_consA[q];
        uint4 cB = g_consB[q];
        uint2 cC = g_consC[q];
        const unsigned we[5] = {cA.x, cA.z, cB.x, cB.z, cC.x};
        const unsigned wo[5] = {cA.y, cA.w, cB.y, cB.w, cC.y};
#pragma unroll
        for (int p = 0; p < 5; ++p) {
            const float celo = bf16lo(we[p]), cehi = bf16hi(we[p]);
            const float colo = bf16lo(wo[p]), cohi = bf16hi(wo[p]);
            accA[2 * p]     = fmaf(f0A, celo, fmaf(f1A, colo, accA[2 * p]));
            accA[2 * p + 1] = fmaf(f0A, cehi, fmaf(f1A, cohi, accA[2 * p + 1]));
            accB[2 * p]     = fmaf(f0B, celo, fmaf(f1B, colo, accB[2 * p]));
            accB[2 * p + 1] = fmaf(f0B, cehi, fmaf(f1B, cohi, accB[2 * p + 1]));
        }
    }

#pragma unroll
    for (int off = 16; off > 0; off >>= 1) {
        sumA += __shfl_xor_sync(0xffffffffu, sumA, off);
        sumB += __shfl_xor_sync(0xffffffffu, sumB, off);
#pragma unroll
        for (int c = 0; c < NC; ++c) {
            accA[c] += __shfl_xor_sync(0xffffffffu, accA[c], off);
            accB[c] += __shfl_xor_sync(0xffffffffu, accB[c], off);
        }
    }
    if (lane == 0) {
        s_sum[w][0] = sumA;
        s_sum[w][1] = sumB;
#pragma unroll
        for (int c = 0; c < NC; ++c) {
            s_acc[w][0][c] = accA[c];
            s_acc[w][1][c] = accB[c];
        }
    }
    __syncthreads();

    const float totA = s_sum[0][0] + s_sum[1][0] + s_sum[2][0] + s_sum[3][0];
    const float totB = s_sum[0][1] + s_sum[1][1] + s_sum[2][1] + s_sum[3][1];
    const float invA = 1.f / (totA + 1e-9f);
    const float invB = 1.f / (totB + 1e-9f);

    // ---- PASS 2: normalize parked f -> STG.128 ----
    // lane owns 2 adjacent pairs (own warp's range, already synced)
    float4* npA = (float4*)(norm_out + (size_t)bA * NR);
    float4* npB = (float4*)(norm_out + (size_t)bB * NR);
#pragma unroll
    for (int kk = 0; kk < 4; ++kk) {
        const int q2 = (w * 4 + kk) * 64 + lane * 2;    // even pair index
        float4 fA = *(const float4*)&s_f[0][q2];        // LDS.128 (2 pairs)
        float4 fB = *(const float4*)&s_f[1][q2];
        fA.x *= invA; fA.y *= invA; fA.z *= invA; fA.w *= invA;
        fB.x *= invB; fB.y *= invB; fB.z *= invB; fB.w *= invB;
        npA[q2 >> 1] = fA;                              // STG.128
        npB[q2 >> 1] = fB;
    }

    // ---- output: acc on unnormalized f -> (a + MU*tot)*inv*sx ----
    if (tid < 20) {
        const int h = tid / 10, c = tid % 10;
        float a = s_acc[0][h][c] + s_acc[1][h][c] +
                  s_acc[2][h][c] + s_acc[3][h][c];
        float tot = h ? totB : totA;
        float inv = h ? invB : invA;
        out[(size_t)(bA + h) * NC + c] = (a + MU * tot) * inv * s_sx[h];
    }
}

// ---------------------------------------------------------------------------
extern "C" void kernel_launch(void* const* d_in, const int* in_sizes, int n_in,
                              void* d_out, int out_size) {
    const float* x       = (const float*)d_in[0];
    const float* centers = (const float*)d_in[1];
    const float* widths  = (const float*)d_in[2];
    const float* cons    = (const float*)d_in[3];
    const int*   rules   = (const int*)d_in[4];
    float* out = (float*)d_out;

    const long long TOTAL = (long long)NB_B * NC + (long long)NB_B * NR +
                            (long long)NB_B * NDP1;

    float* out_p = out;
    float* norm_p;
    float* xext_p = out;
    int write_xext = 0;

    if ((long long)out_size == TOTAL) {
        norm_p = out + (size_t)NB_B * NC;
        xext_p = out + (size_t)NB_B * NC + (size_t)NB_B * NR;
        write_xext = 1;
    } else {
        void* sp = nullptr;
        cudaGetSymbolAddress(&sp, g_norm_scratch);
        norm_p = (float*)sp;
    }

    prep_kernel<<<NR / 16, 256>>>(cons, rules);
    fused_kernel<<<NB_B / 2, 128>>>(x, centers, widths, norm_p,
                                    xext_p, out_p, write_xext);
}